// round 12
// baseline (speedup 1.0000x reference)
#include <cuda_runtime.h>

// Fused quadratic-form SH shading: out[b,p] = n4^T M(b) n4, n4=(nx,ny,nz,1).
// M symmetric -> 10 coefficients computed per-thread from light[b,0..8]
// (warp-uniform loads). Pure HBM stream: __ldg front-batched loads (MLP=24),
// plain STG.128 stores. 128-thread blocks, 8 float4 per thread.

#define C1_ 0.429043f
#define C2_ 0.511664f
#define C3_ 0.743152f
#define C4_ 0.886227f
#define C5_ 0.247708f

#define NBATCH 64
#define WH (512 * 512)
#define V4_PER_PLANE (WH / 4)          // 65536 float4 per plane
#define V4_PER_THREAD 8
#define THREADS 128
#define BLOCKS_X (V4_PER_PLANE / (THREADS * V4_PER_THREAD))  // 64

__device__ __forceinline__ float quad(float x, float y, float z,
                                      float c0, float c1, float c2, float c3,
                                      float c4, float c5, float c6, float c7,
                                      float c8, float c9) {
    return fmaf(c0, x * x, fmaf(c1, y * y, fmaf(c2, z * z,
           fmaf(c3, x * y, fmaf(c4, x * z, fmaf(c5, y * z,
           fmaf(c6, x, fmaf(c7, y, fmaf(c8, z, c9)))))))));
}

__global__ void __launch_bounds__(THREADS) shade_kernel(
    const float* __restrict__ light,    // [B,9]
    const float* __restrict__ normals,  // [B,3,512,512]
    float* __restrict__ out             // [B,1,512,512]
) {
    int b = blockIdx.y;

    // Coefficients from light — warp-uniform loads (L1-hit broadcast).
    const float* L = light + b * 9;
    float L0 = __ldg(L + 0), L1 = __ldg(L + 1), L2 = __ldg(L + 2);
    float L3 = __ldg(L + 3), L4 = __ldg(L + 4), L5 = __ldg(L + 5);
    float L6 = __ldg(L + 6), L7 = __ldg(L + 7), L8 = __ldg(L + 8);

    float c0 = C1_ * L8;                // M00 (x^2)
    float c1 = -C1_ * L8;               // M11 (y^2)
    float c2 = C3_ * L6;                // M22 (z^2)
    float c3 = 2.0f * C1_ * L4;         // 2*M01 (xy)
    float c4 = 2.0f * C1_ * L7;         // 2*M02 (xz)
    float c5 = 2.0f * C1_ * L5;         // 2*M12 (yz)
    float c6 = 2.0f * C2_ * L3;         // 2*M03 (x)
    float c7 = 2.0f * C2_ * L1;         // 2*M13 (y)
    float c8 = 2.0f * C2_ * L2;         // 2*M23 (z)
    float c9 = C4_ * L0 - C5_ * L6;     // M33 (const)

    // Each block covers THREADS*V4_PER_THREAD = 1024 contiguous float4s.
    int v0 = blockIdx.x * (THREADS * V4_PER_THREAD) + threadIdx.x;

    const float4* px = (const float4*)(normals + (size_t)b * 3 * WH);
    const float4* py = px + V4_PER_PLANE;
    const float4* pz = py + V4_PER_PLANE;
    float4* po = (float4*)(out + (size_t)b * WH);

    // Front-batch all 24 streaming loads (MLP=24).
    float4 xv[V4_PER_THREAD], yv[V4_PER_THREAD], zv[V4_PER_THREAD];
#pragma unroll
    for (int i = 0; i < V4_PER_THREAD; i++) xv[i] = __ldg(px + v0 + i * THREADS);
#pragma unroll
    for (int i = 0; i < V4_PER_THREAD; i++) yv[i] = __ldg(py + v0 + i * THREADS);
#pragma unroll
    for (int i = 0; i < V4_PER_THREAD; i++) zv[i] = __ldg(pz + v0 + i * THREADS);

#pragma unroll
    for (int i = 0; i < V4_PER_THREAD; i++) {
        float4 r;
        r.x = quad(xv[i].x, yv[i].x, zv[i].x, c0,c1,c2,c3,c4,c5,c6,c7,c8,c9);
        r.y = quad(xv[i].y, yv[i].y, zv[i].y, c0,c1,c2,c3,c4,c5,c6,c7,c8,c9);
        r.z = quad(xv[i].z, yv[i].z, zv[i].z, c0,c1,c2,c3,c4,c5,c6,c7,c8,c9);
        r.w = quad(xv[i].w, yv[i].w, zv[i].w, c0,c1,c2,c3,c4,c5,c6,c7,c8,c9);
        po[v0 + i * THREADS] = r;
    }
}

extern "C" void kernel_launch(void* const* d_in, const int* in_sizes, int n_in,
                              void* d_out, int out_size) {
    const float* light = (const float*)d_in[0];     // [64,9]
    const float* normals = (const float*)d_in[1];   // [64,3,512,512]
    float* out = (float*)d_out;                     // [64,1,512,512]

    dim3 grid(BLOCKS_X, NBATCH);  // (64, 64)
    shade_kernel<<<grid, THREADS>>>(light, normals, out);
}

// round 13
// speedup vs baseline: 1.0570x; 1.0570x over previous
#include <cuda_runtime.h>

// Fused quadratic-form SH shading: out[b,p] = n4^T M(b) n4, n4=(nx,ny,nz,1).
// M symmetric -> 10 coefficients computed per-thread from light[b,0..8]
// (warp-uniform loads). Pure HBM stream. All 12 LDG.128 front-batched and ALL
// stores deferred to the end, forcing ptxas to keep every loaded value live
// (real MLP=12 in SASS, not just in source).

#define C1_ 0.429043f
#define C2_ 0.511664f
#define C3_ 0.743152f
#define C4_ 0.886227f
#define C5_ 0.247708f

#define NBATCH 64
#define WH (512 * 512)
#define V4_PER_PLANE (WH / 4)          // 65536 float4 per plane
#define V4_PER_THREAD 4
#define THREADS 128
#define BLOCKS_X (V4_PER_PLANE / (THREADS * V4_PER_THREAD))  // 128

__device__ __forceinline__ float quad(float x, float y, float z,
                                      float c0, float c1, float c2, float c3,
                                      float c4, float c5, float c6, float c7,
                                      float c8, float c9) {
    return fmaf(c0, x * x, fmaf(c1, y * y, fmaf(c2, z * z,
           fmaf(c3, x * y, fmaf(c4, x * z, fmaf(c5, y * z,
           fmaf(c6, x, fmaf(c7, y, fmaf(c8, z, c9)))))))));
}

__global__ void __launch_bounds__(THREADS) shade_kernel(
    const float* __restrict__ light,    // [B,9]
    const float* __restrict__ normals,  // [B,3,512,512]
    float* __restrict__ out             // [B,1,512,512]
) {
    int b = blockIdx.y;

    // Coefficients from light — warp-uniform loads (L1-hit broadcast).
    const float* L = light + b * 9;
    float L0 = __ldg(L + 0), L1 = __ldg(L + 1), L2 = __ldg(L + 2);
    float L3 = __ldg(L + 3), L4 = __ldg(L + 4), L5 = __ldg(L + 5);
    float L6 = __ldg(L + 6), L7 = __ldg(L + 7), L8 = __ldg(L + 8);

    float c0 = C1_ * L8;                // M00 (x^2)
    float c1 = -C1_ * L8;               // M11 (y^2)
    float c2 = C3_ * L6;                // M22 (z^2)
    float c3 = 2.0f * C1_ * L4;         // 2*M01 (xy)
    float c4 = 2.0f * C1_ * L7;         // 2*M02 (xz)
    float c5 = 2.0f * C1_ * L5;         // 2*M12 (yz)
    float c6 = 2.0f * C2_ * L3;         // 2*M03 (x)
    float c7 = 2.0f * C2_ * L1;         // 2*M13 (y)
    float c8 = 2.0f * C2_ * L2;         // 2*M23 (z)
    float c9 = C4_ * L0 - C5_ * L6;     // M33 (const)

    // Each block covers THREADS*V4_PER_THREAD = 512 contiguous float4s.
    int v0 = blockIdx.x * (THREADS * V4_PER_THREAD) + threadIdx.x;

    const float4* px = (const float4*)(normals + (size_t)b * 3 * WH);
    const float4* py = px + V4_PER_PLANE;
    const float4* pz = py + V4_PER_PLANE;
    float4* po = (float4*)(out + (size_t)b * WH);

    // Front-batch all 12 streaming loads.
    float4 xv[V4_PER_THREAD], yv[V4_PER_THREAD], zv[V4_PER_THREAD];
#pragma unroll
    for (int i = 0; i < V4_PER_THREAD; i++) xv[i] = __ldg(px + v0 + i * THREADS);
#pragma unroll
    for (int i = 0; i < V4_PER_THREAD; i++) yv[i] = __ldg(py + v0 + i * THREADS);
#pragma unroll
    for (int i = 0; i < V4_PER_THREAD; i++) zv[i] = __ldg(pz + v0 + i * THREADS);

    // Compute ALL results first (keeps every loaded value live -> forces
    // ptxas to emit all 12 LDG.128 up front), then store at the end.
    float4 r[V4_PER_THREAD];
#pragma unroll
    for (int i = 0; i < V4_PER_THREAD; i++) {
        r[i].x = quad(xv[i].x, yv[i].x, zv[i].x, c0,c1,c2,c3,c4,c5,c6,c7,c8,c9);
        r[i].y = quad(xv[i].y, yv[i].y, zv[i].y, c0,c1,c2,c3,c4,c5,c6,c7,c8,c9);
        r[i].z = quad(xv[i].z, yv[i].z, zv[i].z, c0,c1,c2,c3,c4,c5,c6,c7,c8,c9);
        r[i].w = quad(xv[i].w, yv[i].w, zv[i].w, c0,c1,c2,c3,c4,c5,c6,c7,c8,c9);
    }
#pragma unroll
    for (int i = 0; i < V4_PER_THREAD; i++)
        po[v0 + i * THREADS] = r[i];
}

extern "C" void kernel_launch(void* const* d_in, const int* in_sizes, int n_in,
                              void* d_out, int out_size) {
    const float* light = (const float*)d_in[0];     // [64,9]
    const float* normals = (const float*)d_in[1];   // [64,3,512,512]
    float* out = (float*)d_out;                     // [64,1,512,512]

    dim3 grid(BLOCKS_X, NBATCH);  // (128, 64)
    shade_kernel<<<grid, THREADS>>>(light, normals, out);
}